// round 12
// baseline (speedup 1.0000x reference)
#include <cuda_runtime.h>

#define NQ     10
#define NL     4
#define WPB    4
#define BLOCK  (32 * WPB)

typedef unsigned long long u64;

// Per gate: 4 role-combos (rlo,rhi) x 6 packs {ARe,AIm,AImN,BRe,BIm,BImN}
__device__   u64 gPackedBuf[NL * NQ * 24];
__constant__ u64 cG[NL * NQ * 24];
// Layer-0 fused matrices, plain floats: {M00x,M00y,M01x,M01y,M10x,M10y,M11x,M11y}
__device__   float gM0Buf[NQ * 8];
__constant__ float cM0[NQ * 8];

// ============================================================
// Compile-time GF(2) frame tables (semantics verified R8/R9/R10)
// ============================================================
__host__ __device__ constexpr int parc(int v) {
    int c = 0;
    for (int b = 0; b < NQ; ++b) c ^= (v >> b) & 1;
    return c;
}

constexpr int sigma1(int j) {
    int s = j;
    for (int q = 9; q >= 0; --q) {
        int pc = 9 - q;
        int pt = 9 - ((q + 1) % 10);
        s ^= ((s >> pc) & 1) << pt;
    }
    return s;
}

struct MaskTab {
    int m[NL][NQ];
    int sel[NL + 1][NQ];
};

constexpr MaskTab build_masks() {
    MaskTab t{};
    int perm[1024] = {};
    for (int j = 0; j < 1024; ++j) perm[j] = j;
    int inv[1024] = {};
    for (int l = 0; l <= NL; ++l) {
        if (l < NL)
            for (int p = 0; p < NQ; ++p) t.m[l][p] = perm[1 << p];
        for (int j = 0; j < 1024; ++j) inv[perm[j]] = j;
        for (int p = 0; p < NQ; ++p) {
            int s = 0;
            for (int b = 0; b < NQ; ++b) s |= ((inv[1 << b] >> p) & 1) << b;
            t.sel[l][p] = s;
        }
        if (l < NL) {
            int nxt[1024] = {};
            for (int j = 0; j < 1024; ++j) nxt[j] = perm[sigma1(j)];
            for (int j = 0; j < 1024; ++j) perm[j] = nxt[j];
        }
    }
    return t;
}
constexpr MaskTab MT = build_masks();

// ============================================================
// Packed f32x2 helpers
// ============================================================
__device__ __forceinline__ u64 pk2(float a, float b) {
    u64 r; asm("mov.b64 %0, {%1, %2};" : "=l"(r) : "f"(a), "f"(b)); return r;
}
__device__ __forceinline__ void upk(u64 v, float& a, float& b) {
    asm("mov.b64 {%0, %1}, %2;" : "=f"(a), "=f"(b) : "l"(v));
}
__device__ __forceinline__ u64 fma2(u64 a, u64 b, u64 c) {
    u64 d; asm("fma.rn.f32x2 %0, %1, %2, %3;" : "=l"(d) : "l"(a), "l"(b), "l"(c)); return d;
}
__device__ __forceinline__ u64 mul2(u64 a, u64 b) {
    u64 d; asm("mul.rn.f32x2 %0, %1, %2;" : "=l"(d) : "l"(a), "l"(b)); return d;
}
__device__ __forceinline__ u64 swap64(u64 v) {
    union { u64 w; uint2 u; } a;
    a.w = v;
    unsigned t = a.u.x; a.u.x = a.u.y; a.u.y = t;
    return a.w;
}
__device__ __forceinline__ u64 shfl64x(u64 v, int xm) {
    return __shfl_xor_sync(0xffffffffu, v, xm);
}

// ============================================================
// Setup: fuse Rx*Ry*Rz; packs for all gates + raw M for layer 0
// ============================================================
struct c2 { float x, y; };
__device__ __forceinline__ c2 cmulh(c2 a, c2 b) { return { a.x*b.x - a.y*b.y, a.x*b.y + a.y*b.x }; }
__device__ __forceinline__ c2 caddh(c2 a, c2 b) { return { a.x + b.x, a.y + b.y }; }

__global__ void tq_setup_kernel(const float* __restrict__ theta) {
    int t = threadIdx.x;
    if (t >= NL * NQ) return;
    float t0 = theta[t*3+0], t1 = theta[t*3+1], t2 = theta[t*3+2];
    float cx = cosf(0.5f*t0), sx = sinf(0.5f*t0);
    float cy = cosf(0.5f*t1), sy = sinf(0.5f*t1);
    float cz = cosf(0.5f*t2), sz = sinf(0.5f*t2);

    c2 x00{cx,0.f}, x01{0.f,-sx}, x10{0.f,-sx}, x11{cx,0.f};
    c2 y00{cy,0.f}, y01{-sy,0.f}, y10{sy,0.f},  y11{cy,0.f};

    c2 A00 = caddh(cmulh(x00,y00), cmulh(x01,y10));
    c2 A01 = caddh(cmulh(x00,y01), cmulh(x01,y11));
    c2 A10 = caddh(cmulh(x10,y00), cmulh(x11,y10));
    c2 A11 = caddh(cmulh(x10,y01), cmulh(x11,y11));

    c2 e0{cz,-sz}, e1{cz,sz};
    c2 M00 = cmulh(A00,e0), M01 = cmulh(A01,e1);
    c2 M10 = cmulh(A10,e0), M11 = cmulh(A11,e1);

    u64* o = &gPackedBuf[t * 24];
    for (int rlo = 0; rlo < 2; ++rlo)
        for (int rhi = 0; rhi < 2; ++rhi) {
            c2 Alo = rlo ? M11 : M00, Ahi = rhi ? M11 : M00;
            c2 Blo = rlo ? M01 : M10, Bhi = rhi ? M01 : M10;
            u64* p = o + (rlo * 2 + rhi) * 6;
            p[0] = pk2(Alo.x,  Ahi.x);
            p[1] = pk2(Alo.y,  Ahi.y);
            p[2] = pk2(-Alo.y, -Ahi.y);
            p[3] = pk2(Blo.x,  Bhi.x);
            p[4] = pk2(Blo.y,  Bhi.y);
            p[5] = pk2(-Blo.y, -Bhi.y);
        }

    if (t < NQ) {     // layer-0 raw matrices for init absorption
        float* m = &gM0Buf[t * 8];
        m[0] = M00.x; m[1] = M00.y; m[2] = M01.x; m[3] = M01.y;
        m[4] = M10.x; m[5] = M10.y; m[6] = M11.x; m[7] = M11.y;
    }
}

// ============================================================
// One gate, frame-tracked (identical to R10, which passed).
// ============================================================
#define CSEL(R, I) ((R) ? C1_##I : C0_##I)

#define UPDP(X, Y, PX, PY, R) do {                                            \
    u64 _nx = fma2((PY), CSEL(R,5), fma2((PX), CSEL(R,3),                     \
              fma2((Y),  CSEL(R,2), mul2((X),  CSEL(R,0)))));                 \
    u64 _ny = fma2((PY), CSEL(R,3), fma2((PX), CSEL(R,4),                     \
              fma2((Y),  CSEL(R,0), mul2((X),  CSEL(R,1)))));                 \
    (X) = _nx; (Y) = _ny; } while (0)

#define GJ_SELF(J) {                                                          \
    constexpr bool R_ = (selreg != 0) && (parc((J) & selreg) != 0);           \
    u64 px_ = xs[J], py_ = ys[J];                                             \
    if constexpr (mlane != 0) { px_ = shfl64x(px_, mlane);                    \
                                py_ = shfl64x(py_, mlane); }                  \
    if constexpr (mp == 1)    { px_ = swap64(px_); py_ = swap64(py_); }       \
    UPDP(xs[J], ys[J], px_, py_, R_); }

#define GJ_PAIR(J) if constexpr ((((J) & hb) == 0) && mreg != 0) {            \
    constexpr int  J2_ = (J) ^ mreg;                                         \
    constexpr bool RA_ = (selreg != 0) && (parc((J)  & selreg) != 0);         \
    constexpr bool RB_ = (selreg != 0) && (parc(J2_ & selreg) != 0);          \
    u64 pax_ = xs[J2_], pay_ = ys[J2_], pbx_ = xs[J], pby_ = ys[J];           \
    if constexpr (mlane != 0) {                                               \
        pax_ = shfl64x(pax_, mlane); pay_ = shfl64x(pay_, mlane);             \
        pbx_ = shfl64x(pbx_, mlane); pby_ = shfl64x(pby_, mlane); }           \
    if constexpr (mp == 1) {                                                  \
        pax_ = swap64(pax_); pay_ = swap64(pay_);                             \
        pbx_ = swap64(pbx_); pby_ = swap64(pby_); }                           \
    UPDP(xs[J],  ys[J],  pax_, pay_, RA_);                                    \
    UPDP(xs[J2_], ys[J2_], pbx_, pby_, RB_); }

template<int L, int P>
__device__ __forceinline__ void apply_gate(u64* xs, u64* ys, int lane) {
    constexpr int m  = MT.m[L][P];
    constexpr int sl = MT.sel[L][P];
    static_assert(parc(m & sl) == 1, "pair must flip role");
    constexpr int mp = (m >> 9) & 1, mreg = (m >> 5) & 15, mlane = m & 31;
    constexpr int sp = (sl >> 9) & 1, selreg = (sl >> 5) & 15, sellane = sl & 31;
    constexpr int g24 = (L * NQ + (9 - P)) * 24;
    constexpr int i0 = ((0 << 1) | (0 ^ sp)) * 6;
    constexpr int i1 = ((1 << 1) | (1 ^ sp)) * 6;
    constexpr int hb = mreg ? (mreg & (-mreg)) : 1;

    u64 C0_0, C0_1, C0_2, C0_3, C0_4, C0_5;
    u64 C1_0 = 0, C1_1 = 0, C1_2 = 0, C1_3 = 0, C1_4 = 0, C1_5 = 0;
    if constexpr (sellane != 0) {
        const bool lp = (__popc(lane & sellane) & 1) != 0;
        C0_0 = lp ? cG[g24+i1+0] : cG[g24+i0+0];
        C0_1 = lp ? cG[g24+i1+1] : cG[g24+i0+1];
        C0_2 = lp ? cG[g24+i1+2] : cG[g24+i0+2];
        C0_3 = lp ? cG[g24+i1+3] : cG[g24+i0+3];
        C0_4 = lp ? cG[g24+i1+4] : cG[g24+i0+4];
        C0_5 = lp ? cG[g24+i1+5] : cG[g24+i0+5];
        if constexpr (selreg != 0) {
            C1_0 = lp ? cG[g24+i0+0] : cG[g24+i1+0];
            C1_1 = lp ? cG[g24+i0+1] : cG[g24+i1+1];
            C1_2 = lp ? cG[g24+i0+2] : cG[g24+i1+2];
            C1_3 = lp ? cG[g24+i0+3] : cG[g24+i1+3];
            C1_4 = lp ? cG[g24+i0+4] : cG[g24+i1+4];
            C1_5 = lp ? cG[g24+i0+5] : cG[g24+i1+5];
        }
    } else {
        C0_0 = cG[g24+i0+0]; C0_1 = cG[g24+i0+1]; C0_2 = cG[g24+i0+2];
        C0_3 = cG[g24+i0+3]; C0_4 = cG[g24+i0+4]; C0_5 = cG[g24+i0+5];
        if constexpr (selreg != 0) {
            C1_0 = cG[g24+i1+0]; C1_1 = cG[g24+i1+1]; C1_2 = cG[g24+i1+2];
            C1_3 = cG[g24+i1+3]; C1_4 = cG[g24+i1+4]; C1_5 = cG[g24+i1+5];
        }
    }

    if constexpr (mreg == 0) {
        GJ_SELF(0)  GJ_SELF(1)  GJ_SELF(2)  GJ_SELF(3)
        GJ_SELF(4)  GJ_SELF(5)  GJ_SELF(6)  GJ_SELF(7)
        GJ_SELF(8)  GJ_SELF(9)  GJ_SELF(10) GJ_SELF(11)
        GJ_SELF(12) GJ_SELF(13) GJ_SELF(14) GJ_SELF(15)
    } else {
        GJ_PAIR(0)  GJ_PAIR(1)  GJ_PAIR(2)  GJ_PAIR(3)
        GJ_PAIR(4)  GJ_PAIR(5)  GJ_PAIR(6)  GJ_PAIR(7)
        GJ_PAIR(8)  GJ_PAIR(9)  GJ_PAIR(10) GJ_PAIR(11)
        GJ_PAIR(12) GJ_PAIR(13) GJ_PAIR(14) GJ_PAIR(15)
    }
}

template<int L>
__device__ __forceinline__ void layer(u64* xs, u64* ys, int lane) {
    apply_gate<L, 9>(xs, ys, lane);
    apply_gate<L, 8>(xs, ys, lane);
    apply_gate<L, 7>(xs, ys, lane);
    apply_gate<L, 6>(xs, ys, lane);
    apply_gate<L, 5>(xs, ys, lane);
    apply_gate<L, 4>(xs, ys, lane);
    apply_gate<L, 3>(xs, ys, lane);
    apply_gate<L, 2>(xs, ys, lane);
    apply_gate<L, 1>(xs, ys, lane);
    apply_gate<L, 0>(xs, ys, lane);
}

// ============================================================
// Readout (unchanged from R10)
// ============================================================
template<int Q>
__device__ __forceinline__ float readout_one(const u64* pr, int lane) {
    constexpr int sel = MT.sel[NL][9 - Q];
    constexpr int sp  = (sel >> 9) & 1;
    constexpr int sr  = (sel >> 5) & 15;
    constexpr int slq = sel & 31;
    const u64 sPP = pk2(1.f,  sp ? -1.f : 1.f);
    const u64 sNN = pk2(-1.f, sp ? 1.f : -1.f);
    u64 acc = pk2(0.f, 0.f);
#pragma unroll
    for (int j = 0; j < 16; ++j)
        acc = fma2(pr[j], parc(j & sr) ? sNN : sPP, acc);
    float lo, hi; upk(acc, lo, hi);
    float a = lo + hi;
    if constexpr (slq != 0) {
        if (__popc(lane & slq) & 1) a = -a;
    }
#pragma unroll
    for (int off = 16; off; off >>= 1)
        a += __shfl_xor_sync(0xffffffffu, a, off);
    return a;
}

// ============================================================
// Main kernel: layer 0 absorbed into init; 5 CTAs/SM target
// ============================================================
__global__ __launch_bounds__(BLOCK, 5)
void tq_main_kernel(const float* __restrict__ x,
                    const float* __restrict__ W,
                    const float* __restrict__ bias,
                    float* __restrict__ out) {
    const int lane = threadIdx.x & 31;
    const int b    = blockIdx.x * WPB + (threadIdx.x >> 5);

    // per-qubit post-layer-0 2-vectors: v_q = (cos,-sin) @ M0_q  (complex)
    float2 v0[NQ], v1[NQ];
    {
        float x0 = x[b*3+0], x1 = x[b*3+1], x2 = x[b*3+2];
#pragma unroll
        for (int q = 0; q < NQ; ++q) {
            float z = fmaf(x0, W[q*3+0], fmaf(x1, W[q*3+1], fmaf(x2, W[q*3+2], bias[q])));
            float t = 3.14159265358979323846f * tanhf(z);
            float s, c; sincosf(0.5f * t, &s, &c);
            const float* mm = &cM0[q * 8];
            v0[q].x = fmaf(c, mm[0], -s * mm[4]);
            v0[q].y = fmaf(c, mm[1], -s * mm[5]);
            v1[q].x = fmaf(c, mm[2], -s * mm[6]);
            v1[q].y = fmaf(c, mm[3], -s * mm[7]);
        }
    }

    // complex product-state build
    u64 xs[16], ys[16];
    {
        float2 F = (lane & 1) ? v1[9] : v0[9];
#pragma unroll
        for (int p = 1; p < 5; ++p) {
            float2 g = ((lane >> p) & 1) ? v1[9 - p] : v0[9 - p];
            F = make_float2(F.x * g.x - F.y * g.y, F.x * g.y + F.y * g.x);
        }
        float2 af[16];
        af[0] = F;
#pragma unroll
        for (int bit = 0; bit < 4; ++bit) {
            int q = 4 - bit;
#pragma unroll
            for (int k = (1 << bit) - 1; k >= 0; --k) {
                float2 a = af[k];
                af[k | (1 << bit)] = make_float2(a.x * v1[q].x - a.y * v1[q].y,
                                                 a.x * v1[q].y + a.y * v1[q].x);
                af[k]              = make_float2(a.x * v0[q].x - a.y * v0[q].y,
                                                 a.x * v0[q].y + a.y * v0[q].x);
            }
        }
#pragma unroll
        for (int j = 0; j < 16; ++j) {
            float2 a = af[j];
            float lox = a.x * v0[0].x - a.y * v0[0].y;
            float loy = a.x * v0[0].y + a.y * v0[0].x;
            float hix = a.x * v1[0].x - a.y * v1[0].y;
            float hiy = a.x * v1[0].y + a.y * v1[0].x;
            xs[j] = pk2(lox, hix);
            ys[j] = pk2(loy, hiy);
        }
    }

    layer<1>(xs, ys, lane);
    layer<2>(xs, ys, lane);
    layer<3>(xs, ys, lane);

#pragma unroll
    for (int j = 0; j < 16; ++j)
        xs[j] = fma2(ys[j], ys[j], mul2(xs[j], xs[j]));

    float e[NQ];
    e[0] = readout_one<0>(xs, lane);
    e[1] = readout_one<1>(xs, lane);
    e[2] = readout_one<2>(xs, lane);
    e[3] = readout_one<3>(xs, lane);
    e[4] = readout_one<4>(xs, lane);
    e[5] = readout_one<5>(xs, lane);
    e[6] = readout_one<6>(xs, lane);
    e[7] = readout_one<7>(xs, lane);
    e[8] = readout_one<8>(xs, lane);
    e[9] = readout_one<9>(xs, lane);

    if (lane == 0) {
#pragma unroll
        for (int q = 0; q < NQ; ++q) out[b * NQ + q] = e[q];
    }
}

extern "C" void kernel_launch(void* const* d_in, const int* in_sizes, int n_in,
                              void* d_out, int out_size) {
    const float* x     = (const float*)d_in[0];   // [16384, 3]
    const float* enc_W = (const float*)d_in[1];   // [10, 3]
    const float* enc_b = (const float*)d_in[2];   // [10]
    const float* theta = (const float*)d_in[3];   // [4, 10, 3]
    float* out = (float*)d_out;                   // [16384, 10]

    int batch = in_sizes[0] / 3;

    tq_setup_kernel<<<1, 64>>>(theta);

    void* src = nullptr;
    cudaGetSymbolAddress(&src, gPackedBuf);
    cudaMemcpyToSymbolAsync(cG, src, sizeof(u64) * NL * NQ * 24, 0,
                            cudaMemcpyDeviceToDevice, 0);
    void* src0 = nullptr;
    cudaGetSymbolAddress(&src0, gM0Buf);
    cudaMemcpyToSymbolAsync(cM0, src0, sizeof(float) * NQ * 8, 0,
                            cudaMemcpyDeviceToDevice, 0);

    tq_main_kernel<<<batch / WPB, BLOCK>>>(x, enc_W, enc_b, out);
}

// round 13
// speedup vs baseline: 1.8390x; 1.8390x over previous
#include <cuda_runtime.h>

#define NQ     10
#define NL     4
#define WPB    4
#define BLOCK  (32 * WPB)

typedef unsigned long long u64;

// Per gate: 4 role-combos (rlo,rhi) x 6 packs {ARe,AIm,AImN,BRe,BIm,BImN}
__device__   u64 gPackedBuf[NL * NQ * 24];
__constant__ u64 cG[NL * NQ * 24];
// Layer-0 fused matrices, plain floats: {M00x,M00y,M01x,M01y,M10x,M10y,M11x,M11y}
__device__   float gM0Buf[NQ * 8];
__constant__ float cM0[NQ * 8];

// ============================================================
// Compile-time GF(2) frame tables (semantics verified R8/R9/R10)
// ============================================================
__host__ __device__ constexpr int parc(int v) {
    int c = 0;
    for (int b = 0; b < NQ; ++b) c ^= (v >> b) & 1;
    return c;
}

constexpr int sigma1(int j) {
    int s = j;
    for (int q = 9; q >= 0; --q) {
        int pc = 9 - q;
        int pt = 9 - ((q + 1) % 10);
        s ^= ((s >> pc) & 1) << pt;
    }
    return s;
}

struct MaskTab {
    int m[NL][NQ];
    int sel[NL + 1][NQ];
};

constexpr MaskTab build_masks() {
    MaskTab t{};
    int perm[1024] = {};
    for (int j = 0; j < 1024; ++j) perm[j] = j;
    int inv[1024] = {};
    for (int l = 0; l <= NL; ++l) {
        if (l < NL)
            for (int p = 0; p < NQ; ++p) t.m[l][p] = perm[1 << p];
        for (int j = 0; j < 1024; ++j) inv[perm[j]] = j;
        for (int p = 0; p < NQ; ++p) {
            int s = 0;
            for (int b = 0; b < NQ; ++b) s |= ((inv[1 << b] >> p) & 1) << b;
            t.sel[l][p] = s;
        }
        if (l < NL) {
            int nxt[1024] = {};
            for (int j = 0; j < 1024; ++j) nxt[j] = perm[sigma1(j)];
            for (int j = 0; j < 1024; ++j) perm[j] = nxt[j];
        }
    }
    return t;
}
constexpr MaskTab MT = build_masks();

// ============================================================
// Packed f32x2 helpers
// ============================================================
__device__ __forceinline__ u64 pk2(float a, float b) {
    u64 r; asm("mov.b64 %0, {%1, %2};" : "=l"(r) : "f"(a), "f"(b)); return r;
}
__device__ __forceinline__ void upk(u64 v, float& a, float& b) {
    asm("mov.b64 {%0, %1}, %2;" : "=f"(a), "=f"(b) : "l"(v));
}
__device__ __forceinline__ u64 fma2(u64 a, u64 b, u64 c) {
    u64 d; asm("fma.rn.f32x2 %0, %1, %2, %3;" : "=l"(d) : "l"(a), "l"(b), "l"(c)); return d;
}
__device__ __forceinline__ u64 mul2(u64 a, u64 b) {
    u64 d; asm("mul.rn.f32x2 %0, %1, %2;" : "=l"(d) : "l"(a), "l"(b)); return d;
}
__device__ __forceinline__ u64 swap64(u64 v) {
    union { u64 w; uint2 u; } a;
    a.w = v;
    unsigned t = a.u.x; a.u.x = a.u.y; a.u.y = t;
    return a.w;
}
__device__ __forceinline__ u64 shfl64x(u64 v, int xm) {
    return __shfl_xor_sync(0xffffffffu, v, xm);
}

// ============================================================
// Setup: fuse Rx*Ry*Rz; packs for all gates + raw M for layer 0
// ============================================================
struct c2 { float x, y; };
__device__ __forceinline__ c2 cmulh(c2 a, c2 b) { return { a.x*b.x - a.y*b.y, a.x*b.y + a.y*b.x }; }
__device__ __forceinline__ c2 caddh(c2 a, c2 b) { return { a.x + b.x, a.y + b.y }; }

__global__ void tq_setup_kernel(const float* __restrict__ theta) {
    int t = threadIdx.x;
    if (t >= NL * NQ) return;
    float t0 = theta[t*3+0], t1 = theta[t*3+1], t2 = theta[t*3+2];
    float cx = cosf(0.5f*t0), sx = sinf(0.5f*t0);
    float cy = cosf(0.5f*t1), sy = sinf(0.5f*t1);
    float cz = cosf(0.5f*t2), sz = sinf(0.5f*t2);

    c2 x00{cx,0.f}, x01{0.f,-sx}, x10{0.f,-sx}, x11{cx,0.f};
    c2 y00{cy,0.f}, y01{-sy,0.f}, y10{sy,0.f},  y11{cy,0.f};

    c2 A00 = caddh(cmulh(x00,y00), cmulh(x01,y10));
    c2 A01 = caddh(cmulh(x00,y01), cmulh(x01,y11));
    c2 A10 = caddh(cmulh(x10,y00), cmulh(x11,y10));
    c2 A11 = caddh(cmulh(x10,y01), cmulh(x11,y11));

    c2 e0{cz,-sz}, e1{cz,sz};
    c2 M00 = cmulh(A00,e0), M01 = cmulh(A01,e1);
    c2 M10 = cmulh(A10,e0), M11 = cmulh(A11,e1);

    u64* o = &gPackedBuf[t * 24];
    for (int rlo = 0; rlo < 2; ++rlo)
        for (int rhi = 0; rhi < 2; ++rhi) {
            c2 Alo = rlo ? M11 : M00, Ahi = rhi ? M11 : M00;
            c2 Blo = rlo ? M01 : M10, Bhi = rhi ? M01 : M10;
            u64* p = o + (rlo * 2 + rhi) * 6;
            p[0] = pk2(Alo.x,  Ahi.x);
            p[1] = pk2(Alo.y,  Ahi.y);
            p[2] = pk2(-Alo.y, -Ahi.y);
            p[3] = pk2(Blo.x,  Bhi.x);
            p[4] = pk2(Blo.y,  Bhi.y);
            p[5] = pk2(-Blo.y, -Bhi.y);
        }

    if (t < NQ) {     // layer-0 raw matrices for init absorption
        float* m = &gM0Buf[t * 8];
        m[0] = M00.x; m[1] = M00.y; m[2] = M01.x; m[3] = M01.y;
        m[4] = M10.x; m[5] = M10.y; m[6] = M11.x; m[7] = M11.y;
    }
}

// ============================================================
// One gate, frame-tracked (identical to R10, which passed).
// ============================================================
#define CSEL(R, I) ((R) ? C1_##I : C0_##I)

#define UPDP(X, Y, PX, PY, R) do {                                            \
    u64 _nx = fma2((PY), CSEL(R,5), fma2((PX), CSEL(R,3),                     \
              fma2((Y),  CSEL(R,2), mul2((X),  CSEL(R,0)))));                 \
    u64 _ny = fma2((PY), CSEL(R,3), fma2((PX), CSEL(R,4),                     \
              fma2((Y),  CSEL(R,0), mul2((X),  CSEL(R,1)))));                 \
    (X) = _nx; (Y) = _ny; } while (0)

#define GJ_SELF(J) {                                                          \
    constexpr bool R_ = (selreg != 0) && (parc((J) & selreg) != 0);           \
    u64 px_ = xs[J], py_ = ys[J];                                             \
    if constexpr (mlane != 0) { px_ = shfl64x(px_, mlane);                    \
                                py_ = shfl64x(py_, mlane); }                  \
    if constexpr (mp == 1)    { px_ = swap64(px_); py_ = swap64(py_); }       \
    UPDP(xs[J], ys[J], px_, py_, R_); }

#define GJ_PAIR(J) if constexpr ((((J) & hb) == 0) && mreg != 0) {            \
    constexpr int  J2_ = (J) ^ mreg;                                         \
    constexpr bool RA_ = (selreg != 0) && (parc((J)  & selreg) != 0);         \
    constexpr bool RB_ = (selreg != 0) && (parc(J2_ & selreg) != 0);          \
    u64 pax_ = xs[J2_], pay_ = ys[J2_], pbx_ = xs[J], pby_ = ys[J];           \
    if constexpr (mlane != 0) {                                               \
        pax_ = shfl64x(pax_, mlane); pay_ = shfl64x(pay_, mlane);             \
        pbx_ = shfl64x(pbx_, mlane); pby_ = shfl64x(pby_, mlane); }           \
    if constexpr (mp == 1) {                                                  \
        pax_ = swap64(pax_); pay_ = swap64(pay_);                             \
        pbx_ = swap64(pbx_); pby_ = swap64(pby_); }                           \
    UPDP(xs[J],  ys[J],  pax_, pay_, RA_);                                    \
    UPDP(xs[J2_], ys[J2_], pbx_, pby_, RB_); }

template<int L, int P>
__device__ __forceinline__ void apply_gate(u64* xs, u64* ys, int lane) {
    constexpr int m  = MT.m[L][P];
    constexpr int sl = MT.sel[L][P];
    static_assert(parc(m & sl) == 1, "pair must flip role");
    constexpr int mp = (m >> 9) & 1, mreg = (m >> 5) & 15, mlane = m & 31;
    constexpr int sp = (sl >> 9) & 1, selreg = (sl >> 5) & 15, sellane = sl & 31;
    constexpr int g24 = (L * NQ + (9 - P)) * 24;
    constexpr int i0 = ((0 << 1) | (0 ^ sp)) * 6;
    constexpr int i1 = ((1 << 1) | (1 ^ sp)) * 6;
    constexpr int hb = mreg ? (mreg & (-mreg)) : 1;

    u64 C0_0, C0_1, C0_2, C0_3, C0_4, C0_5;
    u64 C1_0 = 0, C1_1 = 0, C1_2 = 0, C1_3 = 0, C1_4 = 0, C1_5 = 0;
    if constexpr (sellane != 0) {
        const bool lp = (__popc(lane & sellane) & 1) != 0;
        C0_0 = lp ? cG[g24+i1+0] : cG[g24+i0+0];
        C0_1 = lp ? cG[g24+i1+1] : cG[g24+i0+1];
        C0_2 = lp ? cG[g24+i1+2] : cG[g24+i0+2];
        C0_3 = lp ? cG[g24+i1+3] : cG[g24+i0+3];
        C0_4 = lp ? cG[g24+i1+4] : cG[g24+i0+4];
        C0_5 = lp ? cG[g24+i1+5] : cG[g24+i0+5];
        if constexpr (selreg != 0) {
            C1_0 = lp ? cG[g24+i0+0] : cG[g24+i1+0];
            C1_1 = lp ? cG[g24+i0+1] : cG[g24+i1+1];
            C1_2 = lp ? cG[g24+i0+2] : cG[g24+i1+2];
            C1_3 = lp ? cG[g24+i0+3] : cG[g24+i1+3];
            C1_4 = lp ? cG[g24+i0+4] : cG[g24+i1+4];
            C1_5 = lp ? cG[g24+i0+5] : cG[g24+i1+5];
        }
    } else {
        C0_0 = cG[g24+i0+0]; C0_1 = cG[g24+i0+1]; C0_2 = cG[g24+i0+2];
        C0_3 = cG[g24+i0+3]; C0_4 = cG[g24+i0+4]; C0_5 = cG[g24+i0+5];
        if constexpr (selreg != 0) {
            C1_0 = cG[g24+i1+0]; C1_1 = cG[g24+i1+1]; C1_2 = cG[g24+i1+2];
            C1_3 = cG[g24+i1+3]; C1_4 = cG[g24+i1+4]; C1_5 = cG[g24+i1+5];
        }
    }

    if constexpr (mreg == 0) {
        GJ_SELF(0)  GJ_SELF(1)  GJ_SELF(2)  GJ_SELF(3)
        GJ_SELF(4)  GJ_SELF(5)  GJ_SELF(6)  GJ_SELF(7)
        GJ_SELF(8)  GJ_SELF(9)  GJ_SELF(10) GJ_SELF(11)
        GJ_SELF(12) GJ_SELF(13) GJ_SELF(14) GJ_SELF(15)
    } else {
        GJ_PAIR(0)  GJ_PAIR(1)  GJ_PAIR(2)  GJ_PAIR(3)
        GJ_PAIR(4)  GJ_PAIR(5)  GJ_PAIR(6)  GJ_PAIR(7)
        GJ_PAIR(8)  GJ_PAIR(9)  GJ_PAIR(10) GJ_PAIR(11)
        GJ_PAIR(12) GJ_PAIR(13) GJ_PAIR(14) GJ_PAIR(15)
    }
}

// ============================================================
// Layers: gates within a layer commute (disjoint qubits), so the
// order is free. Interleave register-pure gates (pure FMA) between
// lane-crossing gates (shuffle-heavy) to overlap MIO and FMA pipes.
// Reg-pure from the sigma masks: L1 {P9,P8,P7,P6}, L2 {P9,P8,P7},
// L3 {P9,P8}; all others lane-crossing.
// ============================================================
template<int L>
__device__ __forceinline__ void layer(u64* xs, u64* ys, int lane) {
    if constexpr (L == 1) {
        apply_gate<L, 5>(xs, ys, lane);   // lane
        apply_gate<L, 9>(xs, ys, lane);   // reg
        apply_gate<L, 4>(xs, ys, lane);   // lane
        apply_gate<L, 8>(xs, ys, lane);   // reg
        apply_gate<L, 3>(xs, ys, lane);   // lane
        apply_gate<L, 7>(xs, ys, lane);   // reg
        apply_gate<L, 2>(xs, ys, lane);   // lane
        apply_gate<L, 6>(xs, ys, lane);   // reg
        apply_gate<L, 1>(xs, ys, lane);   // lane
        apply_gate<L, 0>(xs, ys, lane);   // lane
    } else if constexpr (L == 2) {
        apply_gate<L, 6>(xs, ys, lane);   // lane
        apply_gate<L, 9>(xs, ys, lane);   // reg
        apply_gate<L, 5>(xs, ys, lane);   // lane
        apply_gate<L, 8>(xs, ys, lane);   // reg
        apply_gate<L, 4>(xs, ys, lane);   // lane
        apply_gate<L, 7>(xs, ys, lane);   // reg
        apply_gate<L, 3>(xs, ys, lane);   // lane
        apply_gate<L, 2>(xs, ys, lane);   // lane
        apply_gate<L, 1>(xs, ys, lane);   // lane
        apply_gate<L, 0>(xs, ys, lane);   // lane
    } else {
        apply_gate<L, 7>(xs, ys, lane);   // lane
        apply_gate<L, 9>(xs, ys, lane);   // reg
        apply_gate<L, 6>(xs, ys, lane);   // lane
        apply_gate<L, 8>(xs, ys, lane);   // reg
        apply_gate<L, 5>(xs, ys, lane);   // lane
        apply_gate<L, 4>(xs, ys, lane);   // lane
        apply_gate<L, 3>(xs, ys, lane);   // lane
        apply_gate<L, 2>(xs, ys, lane);   // lane
        apply_gate<L, 1>(xs, ys, lane);   // lane
        apply_gate<L, 0>(xs, ys, lane);   // lane
    }
}

// ============================================================
// Readout (unchanged from R10)
// ============================================================
template<int Q>
__device__ __forceinline__ float readout_one(const u64* pr, int lane) {
    constexpr int sel = MT.sel[NL][9 - Q];
    constexpr int sp  = (sel >> 9) & 1;
    constexpr int sr  = (sel >> 5) & 15;
    constexpr int slq = sel & 31;
    const u64 sPP = pk2(1.f,  sp ? -1.f : 1.f);
    const u64 sNN = pk2(-1.f, sp ? 1.f : -1.f);
    u64 acc = pk2(0.f, 0.f);
#pragma unroll
    for (int j = 0; j < 16; ++j)
        acc = fma2(pr[j], parc(j & sr) ? sNN : sPP, acc);
    float lo, hi; upk(acc, lo, hi);
    float a = lo + hi;
    if constexpr (slq != 0) {
        if (__popc(lane & slq) & 1) a = -a;
    }
#pragma unroll
    for (int off = 16; off; off >>= 1)
        a += __shfl_xor_sync(0xffffffffu, a, off);
    return a;
}

// ============================================================
// Main kernel: layer 0 absorbed into init (R10 config: 4 CTAs/SM)
// ============================================================
__global__ __launch_bounds__(BLOCK, 4)
void tq_main_kernel(const float* __restrict__ x,
                    const float* __restrict__ W,
                    const float* __restrict__ bias,
                    float* __restrict__ out) {
    const int lane = threadIdx.x & 31;
    const int b    = blockIdx.x * WPB + (threadIdx.x >> 5);

    // per-qubit post-layer-0 2-vectors: v_q = (cos,-sin) @ M0_q  (complex)
    float2 v0[NQ], v1[NQ];
    {
        float x0 = x[b*3+0], x1 = x[b*3+1], x2 = x[b*3+2];
#pragma unroll
        for (int q = 0; q < NQ; ++q) {
            float z = fmaf(x0, W[q*3+0], fmaf(x1, W[q*3+1], fmaf(x2, W[q*3+2], bias[q])));
            float t = 3.14159265358979323846f * tanhf(z);
            float s, c; sincosf(0.5f * t, &s, &c);
            const float* mm = &cM0[q * 8];
            v0[q].x = fmaf(c, mm[0], -s * mm[4]);
            v0[q].y = fmaf(c, mm[1], -s * mm[5]);
            v1[q].x = fmaf(c, mm[2], -s * mm[6]);
            v1[q].y = fmaf(c, mm[3], -s * mm[7]);
        }
    }

    // complex product-state build
    u64 xs[16], ys[16];
    {
        float2 F = (lane & 1) ? v1[9] : v0[9];
#pragma unroll
        for (int p = 1; p < 5; ++p) {
            float2 g = ((lane >> p) & 1) ? v1[9 - p] : v0[9 - p];
            F = make_float2(F.x * g.x - F.y * g.y, F.x * g.y + F.y * g.x);
        }
        float2 af[16];
        af[0] = F;
#pragma unroll
        for (int bit = 0; bit < 4; ++bit) {
            int q = 4 - bit;
#pragma unroll
            for (int k = (1 << bit) - 1; k >= 0; --k) {
                float2 a = af[k];
                af[k | (1 << bit)] = make_float2(a.x * v1[q].x - a.y * v1[q].y,
                                                 a.x * v1[q].y + a.y * v1[q].x);
                af[k]              = make_float2(a.x * v0[q].x - a.y * v0[q].y,
                                                 a.x * v0[q].y + a.y * v0[q].x);
            }
        }
#pragma unroll
        for (int j = 0; j < 16; ++j) {
            float2 a = af[j];
            float lox = a.x * v0[0].x - a.y * v0[0].y;
            float loy = a.x * v0[0].y + a.y * v0[0].x;
            float hix = a.x * v1[0].x - a.y * v1[0].y;
            float hiy = a.x * v1[0].y + a.y * v1[0].x;
            xs[j] = pk2(lox, hix);
            ys[j] = pk2(loy, hiy);
        }
    }

    layer<1>(xs, ys, lane);
    layer<2>(xs, ys, lane);
    layer<3>(xs, ys, lane);

#pragma unroll
    for (int j = 0; j < 16; ++j)
        xs[j] = fma2(ys[j], ys[j], mul2(xs[j], xs[j]));

    float e[NQ];
    e[0] = readout_one<0>(xs, lane);
    e[1] = readout_one<1>(xs, lane);
    e[2] = readout_one<2>(xs, lane);
    e[3] = readout_one<3>(xs, lane);
    e[4] = readout_one<4>(xs, lane);
    e[5] = readout_one<5>(xs, lane);
    e[6] = readout_one<6>(xs, lane);
    e[7] = readout_one<7>(xs, lane);
    e[8] = readout_one<8>(xs, lane);
    e[9] = readout_one<9>(xs, lane);

    if (lane == 0) {
#pragma unroll
        for (int q = 0; q < NQ; ++q) out[b * NQ + q] = e[q];
    }
}

extern "C" void kernel_launch(void* const* d_in, const int* in_sizes, int n_in,
                              void* d_out, int out_size) {
    const float* x     = (const float*)d_in[0];   // [16384, 3]
    const float* enc_W = (const float*)d_in[1];   // [10, 3]
    const float* enc_b = (const float*)d_in[2];   // [10]
    const float* theta = (const float*)d_in[3];   // [4, 10, 3]
    float* out = (float*)d_out;                   // [16384, 10]

    int batch = in_sizes[0] / 3;

    tq_setup_kernel<<<1, 64>>>(theta);

    void* src = nullptr;
    cudaGetSymbolAddress(&src, gPackedBuf);
    cudaMemcpyToSymbolAsync(cG, src, sizeof(u64) * NL * NQ * 24, 0,
                            cudaMemcpyDeviceToDevice, 0);
    void* src0 = nullptr;
    cudaGetSymbolAddress(&src0, gM0Buf);
    cudaMemcpyToSymbolAsync(cM0, src0, sizeof(float) * NQ * 8, 0,
                            cudaMemcpyDeviceToDevice, 0);

    tq_main_kernel<<<batch / WPB, BLOCK>>>(x, enc_W, enc_b, out);
}